// round 15
// baseline (speedup 1.0000x reference)
#include <cuda_runtime.h>
#include <cuda_bf16.h>
#include <math.h>
#include <stdint.h>

// Problem constants
#define NB    4
#define TSEQ  1024
#define CDIM  1024
#define NH    16
#define DH    64
#define MROWS (NB * TSEQ)      // 4096
#define KDIM  1024

// Scratch (device globals -- no allocation allowed)
__device__ __nv_bfloat16 g_Xhi[(size_t)MROWS * KDIM];
__device__ __nv_bfloat16 g_Xlo[(size_t)MROWS * KDIM];
__device__ __nv_bfloat16 g_Yhi[(size_t)MROWS * KDIM];
__device__ __nv_bfloat16 g_Ylo[(size_t)MROWS * KDIM];
__device__ __nv_bfloat16 g_WAhi[(size_t)KDIM * 3 * CDIM];   // w_attn [k][n] (natural)
__device__ __nv_bfloat16 g_WAlo[(size_t)KDIM * 3 * CDIM];
__device__ __nv_bfloat16 g_WPhi[(size_t)KDIM * CDIM];       // w_proj [k][n] (natural)
__device__ __nv_bfloat16 g_WPlo[(size_t)KDIM * CDIM];
__device__ __nv_bfloat16 g_Qh[(size_t)NB * NH * TSEQ * DH];
__device__ __nv_bfloat16 g_Qlo[(size_t)NB * NH * TSEQ * DH];
__device__ __nv_bfloat16 g_Kh[(size_t)NB * NH * TSEQ * DH];
__device__ __nv_bfloat16 g_Klo[(size_t)NB * NH * TSEQ * DH];
__device__ __nv_bfloat16 g_Vh[(size_t)NB * NH * TSEQ * DH];   // [bh][t][d]
__device__ __nv_bfloat16 g_Vlo[(size_t)NB * NH * TSEQ * DH];

// ---------------------------------------------------------------------------
// Helpers
// ---------------------------------------------------------------------------
__device__ __forceinline__ uint32_t smem_u32(const void* p) {
    return (uint32_t)__cvta_generic_to_shared(p);
}

__device__ __forceinline__ void cp_async16(uint32_t saddr, const void* gptr) {
    asm volatile("cp.async.cg.shared.global [%0], [%1], 16;" :: "r"(saddr), "l"(gptr));
}
#define CP_COMMIT() asm volatile("cp.async.commit_group;" ::: "memory")

__device__ __forceinline__ void ldsm_x4(uint32_t* r, uint32_t addr) {
    asm volatile("ldmatrix.sync.aligned.m8n8.x4.shared.b16 {%0,%1,%2,%3}, [%4];"
                 : "=r"(r[0]), "=r"(r[1]), "=r"(r[2]), "=r"(r[3]) : "r"(addr));
}

__device__ __forceinline__ void ldsm_x4_trans(uint32_t* r, uint32_t addr) {
    asm volatile("ldmatrix.sync.aligned.m8n8.x4.trans.shared.b16 {%0,%1,%2,%3}, [%4];"
                 : "=r"(r[0]), "=r"(r[1]), "=r"(r[2]), "=r"(r[3]) : "r"(addr));
}

__device__ __forceinline__ void mma_bf16(float* c, const uint32_t* a,
                                         uint32_t b0, uint32_t b1) {
    asm volatile(
        "mma.sync.aligned.m16n8k16.row.col.f32.bf16.bf16.f32 "
        "{%0,%1,%2,%3}, {%4,%5,%6,%7}, {%8,%9}, {%0,%1,%2,%3};"
        : "+f"(c[0]), "+f"(c[1]), "+f"(c[2]), "+f"(c[3])
        : "r"(a[0]), "r"(a[1]), "r"(a[2]), "r"(a[3]), "r"(b0), "r"(b1));
}

__device__ __forceinline__ void bsplit(float f, __nv_bfloat16& h, __nv_bfloat16& l) {
    h = __float2bfloat16_rn(f);
    l = __float2bfloat16_rn(f - __bfloat162float(h));
}

__device__ __forceinline__ float fast_exp2(float x) {
    float r;
    asm("ex2.approx.ftz.f32 %0, %1;" : "=f"(r) : "f"(x));
    return r;
}

// ---------------------------------------------------------------------------
// Fused preprocessing: pure elementwise bf16 split (NO transposes).
// ---------------------------------------------------------------------------
__device__ __forceinline__ void split4(const float* __restrict__ s,
        __nv_bfloat16* dh, __nv_bfloat16* dl, size_t i)
{
    float4 v = *(const float4*)(s + i);
    __nv_bfloat16 h0, l0, h1, l1, h2, l2, h3, l3;
    bsplit(v.x, h0, l0); bsplit(v.y, h1, l1);
    bsplit(v.z, h2, l2); bsplit(v.w, h3, l3);
    __nv_bfloat162* ph = (__nv_bfloat162*)(dh + i);
    __nv_bfloat162* pl = (__nv_bfloat162*)(dl + i);
    __nv_bfloat162 a; a.x = h0; a.y = h1;
    __nv_bfloat162 b; b.x = h2; b.y = h3;
    ph[0] = a; ph[1] = b;
    a.x = l0; a.y = l1; b.x = l2; b.y = l3;
    pl[0] = a; pl[1] = b;
}

__global__ __launch_bounds__(256) void preproc_kernel(const float* __restrict__ x,
        const float* __restrict__ wa, const float* __restrict__ wp)
{
    const int bid = blockIdx.x;
    const int tid = threadIdx.x;
    if (bid < 3072) {
        size_t i = ((size_t)bid * 256 + tid) * 4;
        split4(wa, g_WAhi, g_WAlo, i);
    } else if (bid < 4096) {
        size_t i = ((size_t)(bid - 3072) * 256 + tid) * 4;
        split4(wp, g_WPhi, g_WPlo, i);
    } else {
        size_t i = ((size_t)(bid - 4096) * 256 + tid) * 4;
        split4(x, g_Xhi, g_Xlo, i);
    }
}

// ---------------------------------------------------------------------------
// 3xBF16 mma.sync GEMM, BN templated.
// BN=64:  BPANEL 4K, stage 24K, 3 stages = 72K  -> 3 CTAs/SM (QKV)
// BN=128: BPANEL 8K, stage 32K, 3 stages = 96K  -> 2 CTAs/SM (proj)
// A: [m][k] hi/lo; B: natural [k][n] hi/lo via ldmatrix.trans.
// 8 warps (4m x 2n).
// ---------------------------------------------------------------------------
#define GBM 128
#define GBK 32
#define KTILES  (KDIM / GBK)            // 32
#define APANEL  8192                     // 128r x 64B

__device__ __forceinline__ uint32_t sw64(int row, int ch) {
    return (uint32_t)row * 64 + (uint32_t)((ch ^ ((row >> 1) & 3)) << 4);
}
// B panel: rows of BN*2 bytes (BN/8 chunks), chunk ^= row & (BN/8 - 1)
template <int BN>
__device__ __forceinline__ uint32_t swB(int row, int ch) {
    return (uint32_t)row * (BN * 2) + (uint32_t)((ch ^ (row & (BN / 8 - 1))) << 4);
}

template <int N, int BN>
__device__ __forceinline__ void load_tile_b(uint32_t sg,
        const __nv_bfloat16* Ah, const __nv_bfloat16* Al,
        const __nv_bfloat16* Bh, const __nv_bfloat16* Bl,
        int k0, int tid)
{
    constexpr int NCH = BN / 8;                  // B chunks per k-row
    constexpr int BPANEL = 32 * BN * 2;
    constexpr int OBH = 2 * APANEL;
    constexpr int OBL = OBH + BPANEL;
    constexpr int TOT = 1024 + 2 * 32 * NCH;     // total 16B transfers
#pragma unroll
    for (int l = 0; l < TOT / 256; l++) {
        int idx = tid + l * 256;
        if (idx < 1024) {
            int panel = idx >> 9;
            int rem = idx & 511;
            int row = rem >> 2;
            int ch  = rem & 3;
            cp_async16(sg + (panel ? APANEL : 0) + sw64(row, ch),
                       (panel ? Al : Ah) + (size_t)row * KDIM + k0 + ch * 8);
        } else {
            int rem = idx - 1024;                 // 0 .. 2*32*NCH-1
            int panel = rem / (32 * NCH);
            int rem2 = rem % (32 * NCH);
            int row = rem2 / NCH;
            int ch  = rem2 % NCH;
            cp_async16(sg + (panel ? OBL : OBH) + swB<BN>(row, ch),
                       (panel ? Bl : Bh) + (size_t)(k0 + row) * N + ch * 8);
        }
    }
}

template <int N, int MODE, int BN, int MINCTAS>
__global__ __launch_bounds__(256, MINCTAS) void tc_gemm(const float* __restrict__ bias,
                                                        float* __restrict__ out)
{
    constexpr int BPANEL = 32 * BN * 2;
    constexpr int STAGE = 2 * APANEL + 2 * BPANEL;
    constexpr int OBH = 2 * APANEL;
    constexpr int OBL = OBH + BPANEL;
    constexpr int NPW = (BN / 2) / 8;            // n-frags per warp (4 or 8)

    extern __shared__ char smem[];
    const uint32_t sbase = smem_u32(smem);
    const int tid  = threadIdx.x;
    const int warp = tid >> 5;
    const int lane = tid & 31;
    const int wm = warp >> 1;             // 0..3
    const int wn = warp & 1;              // 0..1
    const int bm = blockIdx.y * GBM;
    const int bn = blockIdx.x * BN;

    const __nv_bfloat16* Ah = ((MODE == 0) ? g_Xhi : g_Yhi) + (size_t)bm * KDIM;
    const __nv_bfloat16* Al = ((MODE == 0) ? g_Xlo : g_Ylo) + (size_t)bm * KDIM;
    const __nv_bfloat16* Bh = ((MODE == 0) ? g_WAhi : g_WPhi) + bn;
    const __nv_bfloat16* Bl = ((MODE == 0) ? g_WAlo : g_WPlo) + bn;

    const int arow = wm * 32 + (lane & 15);
    const int acb = (lane >> 4) & 1;
    const int koffG = (((lane >> 3) & 1) << 3) + (lane & 7);
    const int noctG = lane >> 4;

    float acc[2][NPW][4];
#pragma unroll
    for (int mi = 0; mi < 2; mi++)
#pragma unroll
        for (int ni = 0; ni < NPW; ni++)
#pragma unroll
            for (int r = 0; r < 4; r++) acc[mi][ni][r] = 0.0f;

#pragma unroll
    for (int t = 0; t < 2; t++) {
        load_tile_b<N, BN>(sbase + t * STAGE, Ah, Al, Bh, Bl, t * GBK, tid);
        CP_COMMIT();
    }

    for (int t = 0; t < KTILES; t++) {
        if (t < KTILES - 2)
            asm volatile("cp.async.wait_group 1;" ::: "memory");
        else
            asm volatile("cp.async.wait_group 0;" ::: "memory");
        __syncthreads();

        const uint32_t sg = sbase + (uint32_t)(t % 3) * STAGE;

#pragma unroll
        for (int ks = 0; ks < 2; ks++) {
            uint32_t ah[2][4], al[2][4];
#pragma unroll
            for (int mi = 0; mi < 2; mi++) {
                uint32_t ao = sw64(arow + mi * 16, ks * 2 + acb);
                ldsm_x4(ah[mi], sg + 0 + ao);
                ldsm_x4(al[mi], sg + APANEL + ao);
            }
#pragma unroll
            for (int pi = 0; pi < NPW / 2; pi++) {
                uint32_t bh[4], bl[4];
                int vr = ks * 16 + koffG;
                int chv = wn * NPW + 2 * pi + noctG;
                uint32_t bo = swB<BN>(vr, chv);
                ldsm_x4_trans(bh, sg + OBH + bo);
                ldsm_x4_trans(bl, sg + OBL + bo);
#pragma unroll
                for (int mi = 0; mi < 2; mi++)
#pragma unroll
                    for (int sub = 0; sub < 2; sub++) {
                        const int ni = pi * 2 + sub;
                        const int j0 = sub * 2;
                        mma_bf16(acc[mi][ni], al[mi], bh[j0], bh[j0 + 1]);
                        mma_bf16(acc[mi][ni], ah[mi], bl[j0], bl[j0 + 1]);
                        mma_bf16(acc[mi][ni], ah[mi], bh[j0], bh[j0 + 1]);
                    }
            }
        }

        if (t + 2 < KTILES) {
            load_tile_b<N, BN>(sbase + (uint32_t)((t + 2) % 3) * STAGE,
                               Ah, Al, Bh, Bl, (t + 2) * GBK, tid);
            CP_COMMIT();
        }
    }

    // Epilogue
#pragma unroll
    for (int mi = 0; mi < 2; mi++) {
#pragma unroll
        for (int ni = 0; ni < NPW; ni++) {
            const int col = bn + wn * (BN / 2) + ni * 8 + (lane & 3) * 2;
            float2 bv = *(const float2*)(bias + col);
#pragma unroll
            for (int half = 0; half < 2; half++) {
                const int row = bm + wm * 32 + mi * 16 + (lane >> 2) + half * 8;
                float vx = acc[mi][ni][half * 2 + 0] + bv.x;
                float vy = acc[mi][ni][half * 2 + 1] + bv.y;
                if (MODE == 0) {
                    const int sec  = col >> 10;          // 0=q, 1=k, 2=v
                    const int cc   = col & 1023;
                    const int head = cc >> 6;
                    const int dpos = cc & 63;
                    const int b  = row >> 10;
                    const int tt = row & 1023;
                    const int bh2 = b * NH + head;
                    __nv_bfloat16 hx, lx, hy, ly;
                    bsplit(vx, hx, lx); bsplit(vy, hy, ly);
                    __nv_bfloat16* dh = (sec == 0) ? g_Qh : (sec == 1) ? g_Kh : g_Vh;
                    __nv_bfloat16* dl = (sec == 0) ? g_Qlo : (sec == 1) ? g_Klo : g_Vlo;
                    size_t o = ((size_t)bh2 * TSEQ + tt) * DH + dpos;
                    __nv_bfloat162 hv; hv.x = hx; hv.y = hy;
                    __nv_bfloat162 lv; lv.x = lx; lv.y = ly;
                    *(__nv_bfloat162*)(dh + o) = hv;
                    *(__nv_bfloat162*)(dl + o) = lv;
                } else {
                    float2 v2; v2.x = vx; v2.y = vy;
                    *(float2*)(out + (size_t)row * N + col) = v2;
                }
            }
        }
    }
}

// ---------------------------------------------------------------------------
// Tensor-core flash attention, 3xBF16, register-resident P, double-buffered
// K/V, trans-ldmatrix V. SINGLE __syncthreads per tile: prefetch of kt+1 is
// issued AFTER the barrier (all warps finished compute kt-1, the only reader
// of the target buffer).
// ---------------------------------------------------------------------------
#define ABQ   128
#define ABK   64
#define SQH 0
#define SQL 16384
#define SKV 32768
#define ASMEM 98304

__device__ __forceinline__ void attn_load_kv(uint32_t sbuf,
        const __nv_bfloat16* Khp, const __nv_bfloat16* Klp,
        const __nv_bfloat16* Vhp, const __nv_bfloat16* Vlp,
        int k0, int tid)
{
#pragma unroll
    for (int l = 0; l < 4; l++) {
        int idx = tid + l * 256;
        int panel = idx >> 9;
        int rem = idx & 511;
        int r = rem >> 3, ch = rem & 7;
        uint32_t off = (uint32_t)r * 128 + ch * 16;
        uint32_t sw = off ^ ((off >> 3) & 0x70);
        cp_async16(sbuf + (panel ? 8192 : 0) + sw,
                   (panel ? Klp : Khp) + (size_t)(k0 + r) * DH + ch * 8);
        cp_async16(sbuf + (panel ? 24576 : 16384) + sw,
                   (panel ? Vlp : Vhp) + (size_t)(k0 + r) * DH + ch * 8);
    }
}

__global__ __launch_bounds__(256, 2) void attn_kernel()
{
    extern __shared__ char smc[];
    const uint32_t sb = smem_u32(smc);

    const int qi = gridDim.x - 1 - blockIdx.x;
    const int bh = blockIdx.y;
    const int bb = bh >> 4, hh = bh & 15;
    const __nv_bfloat16* Qhp = g_Qh  + (size_t)bh * TSEQ * DH;
    const __nv_bfloat16* Qlp = g_Qlo + (size_t)bh * TSEQ * DH;
    const __nv_bfloat16* Khp = g_Kh  + (size_t)bh * TSEQ * DH;
    const __nv_bfloat16* Klp = g_Klo + (size_t)bh * TSEQ * DH;
    const __nv_bfloat16* Vhp = g_Vh  + (size_t)bh * TSEQ * DH;
    const __nv_bfloat16* Vlp = g_Vlo + (size_t)bh * TSEQ * DH;

    const int tid  = threadIdx.x;
    const int warp = tid >> 5;
    const int lane = tid & 31;
    const int rA   = lane >> 2;
    const int qcol = (lane & 3) * 2;

    const int acb  = (lane >> 4) & 1;
    const int bcb  = (lane >> 3) & 1;
    const int brow = (lane & 7) + ((lane & 16) >> 1);
    const int koff = (((lane >> 3) & 1) << 3) + (lane & 7);
    const int noct = lane >> 4;

#pragma unroll
    for (int l = 0; l < 8; l++) {
        int idx = tid + l * 256;
        int panel = idx >> 10;
        int rem = idx & 1023;
        int r = rem >> 3, ch = rem & 7;
        uint32_t off = (uint32_t)r * 128 + ch * 16;
        uint32_t sw = off ^ ((off >> 3) & 0x70);
        const __nv_bfloat16* src = (panel ? Qlp : Qhp) + (size_t)(qi * ABQ + r) * DH + ch * 8;
        cp_async16(sb + (panel ? SQL : SQH) + sw, src);
    }
    attn_load_kv(sb + SKV, Khp, Klp, Vhp, Vlp, 0, tid);
    CP_COMMIT();

    float o[8][4];
#pragma unroll
    for (int ni = 0; ni < 8; ni++)
#pragma unroll
        for (int j = 0; j < 4; j++) o[ni][j] = 0.0f;
    float mA = -1e30f, mB = -1e30f, lAcc = 0.0f, lBcc = 0.0f;

    const float CS = 0.18033688011112042f;
    const int ntiles = 2 * qi + 2;

    for (int kt = 0; kt < ntiles; kt++) {
        asm volatile("cp.async.wait_group 0;" ::: "memory");   // prefetch(kt) done
        __syncthreads();                                       // compute(kt-1) done

        if (kt + 1 < ntiles) {
            attn_load_kv(sb + SKV + ((kt + 1) & 1) * 32768,
                         Khp, Klp, Vhp, Vlp, (kt + 1) * ABK, tid);
            CP_COMMIT();
        }

        const uint32_t skv = sb + SKV + (uint32_t)(kt & 1) * 32768;

        if (kt * ABK <= qi * ABQ + warp * 16 + 15) {
            float s[8][4];
#pragma unroll
            for (int ni = 0; ni < 8; ni++)
#pragma unroll
                for (int j = 0; j < 4; j++) s[ni][j] = 0.0f;

            const int aQrow = warp * 16 + (lane & 15);
            const uint32_t a_ro = (uint32_t)aQrow * 128;
            const int a_rx = aQrow & 7;
#pragma unroll
            for (int ks = 0; ks < 4; ks++) {
                uint32_t ah[4], al[4], kh[4][4], kl[4][4];
                uint32_t ao = a_ro + (uint32_t)(((ks * 2 + acb) ^ a_rx) << 4);
                ldsm_x4(ah, sb + SQH + ao);
                ldsm_x4(al, sb + SQL + ao);
#pragma unroll
                for (int pi = 0; pi < 4; pi++) {
                    int br = pi * 16 + brow;
                    uint32_t bo = (uint32_t)br * 128 +
                                  (uint32_t)(((ks * 2 + bcb) ^ (br & 7)) << 4);
                    ldsm_x4(kh[pi], skv + bo);
                    ldsm_x4(kl[pi], skv + 8192 + bo);
                }
#pragma unroll
                for (int ni = 0; ni < 8; ni++) {
                    const int pi = ni >> 1, j0 = (ni & 1) * 2;
                    mma_bf16(s[ni], al, kh[pi][j0], kh[pi][j0 + 1]);
                    mma_bf16(s[ni], ah, kl[pi][j0], kl[pi][j0 + 1]);
                    mma_bf16(s[ni], ah, kh[pi][j0], kh[pi][j0 + 1]);
                }
            }

            const bool needmask = (kt * ABK + ABK - 1 > qi * ABQ + warp * 16);
            const int rowgA = qi * ABQ + warp * 16 + rA;
            const int rowgB = rowgA + 8;
            const int cb = kt * ABK + qcol;
#pragma unroll
            for (int ni = 0; ni < 8; ni++) {
                float z0 = s[ni][0] * CS, z1 = s[ni][1] * CS;
                float z2 = s[ni][2] * CS, z3 = s[ni][3] * CS;
                if (needmask) {
                    int c0 = cb + ni * 8, c1 = c0 + 1;
                    if (c0 > rowgA) z0 = -1e30f;
                    if (c1 > rowgA) z1 = -1e30f;
                    if (c0 > rowgB) z2 = -1e30f;
                    if (c1 > rowgB) z3 = -1e30f;
                }
                s[ni][0] = z0; s[ni][1] = z1; s[ni][2] = z2; s[ni][3] = z3;
            }

            float mtA = -1e30f, mtB = -1e30f;
#pragma unroll
            for (int ni = 0; ni < 8; ni++) {
                mtA = fmaxf(mtA, fmaxf(s[ni][0], s[ni][1]));
                mtB = fmaxf(mtB, fmaxf(s[ni][2], s[ni][3]));
            }
            mtA = fmaxf(mtA, __shfl_xor_sync(0xffffffffu, mtA, 1));
            mtA = fmaxf(mtA, __shfl_xor_sync(0xffffffffu, mtA, 2));
            mtB = fmaxf(mtB, __shfl_xor_sync(0xffffffffu, mtB, 1));
            mtB = fmaxf(mtB, __shfl_xor_sync(0xffffffffu, mtB, 2));

            const float mnA = fmaxf(mA, mtA);
            const float mnB = fmaxf(mB, mtB);
            const float aAl = fast_exp2(mA - mnA);
            const float aBl = fast_exp2(mB - mnB);
            mA = mnA; mB = mnB;

            float psA = 0.0f, psB = 0.0f;
#pragma unroll
            for (int ni = 0; ni < 8; ni++) {
                float p0 = fast_exp2(s[ni][0] - mnA);
                float p1 = fast_exp2(s[ni][1] - mnA);
                float p2 = fast_exp2(s[ni][2] - mnB);
                float p3 = fast_exp2(s[ni][3] - mnB);
                psA += p0 + p1; psB += p2 + p3;
                s[ni][0] = p0; s[ni][1] = p1; s[ni][2] = p2; s[ni][3] = p3;
            }
            psA += __shfl_xor_sync(0xffffffffu, psA, 1);
            psA += __shfl_xor_sync(0xffffffffu, psA, 2);
            psB += __shfl_xor_sync(0xffffffffu, psB, 1);
            psB += __shfl_xor_sync(0xffffffffu, psB, 2);
            lAcc = lAcc * aAl + psA;
            lBcc = lBcc * aBl + psB;

#pragma unroll
            for (int ni = 0; ni < 8; ni++) {
                o[ni][0] *= aAl; o[ni][1] *= aAl;
                o[ni][2] *= aBl; o[ni][3] *= aBl;
            }

#pragma unroll
            for (int j = 0; j < 4; j++) {
                uint32_t pa_h[4], pa_l[4];
#pragma unroll
                for (int half = 0; half < 2; half++) {
                    const float* sp = s[2 * j + half];
                    __nv_bfloat162 h0 = __floats2bfloat162_rn(sp[0], sp[1]);
                    __nv_bfloat162 h1 = __floats2bfloat162_rn(sp[2], sp[3]);
                    __nv_bfloat162 l0 = __floats2bfloat162_rn(
                        sp[0] - __bfloat162float(h0.x), sp[1] - __bfloat162float(h0.y));
                    __nv_bfloat162 l1 = __floats2bfloat162_rn(
                        sp[2] - __bfloat162float(h1.x), sp[3] - __bfloat162float(h1.y));
                    pa_h[half * 2 + 0] = *(uint32_t*)&h0;
                    pa_h[half * 2 + 1] = *(uint32_t*)&h1;
                    pa_l[half * 2 + 0] = *(uint32_t*)&l0;
                    pa_l[half * 2 + 1] = *(uint32_t*)&l1;
                }

                uint32_t vh[4][4], vl[4][4];
                const int vrow = j * 16 + koff;
                const uint32_t vro = (uint32_t)vrow * 128;
                const int v_rx = vrow & 7;
#pragma unroll
                for (int pi = 0; pi < 4; pi++) {
                    uint32_t chv = (uint32_t)(2 * pi + noct);
                    uint32_t bo = vro + ((chv ^ (uint32_t)v_rx) << 4);
                    ldsm_x4_trans(vh[pi], skv + 16384 + bo);
                    ldsm_x4_trans(vl[pi], skv + 24576 + bo);
                }
#pragma unroll
                for (int ni = 0; ni < 8; ni++) {
                    const int pi = ni >> 1, j0 = (ni & 1) * 2;
                    mma_bf16(o[ni], pa_l, vh[pi][j0], vh[pi][j0 + 1]);
                    mma_bf16(o[ni], pa_h, vl[pi][j0], vl[pi][j0 + 1]);
                    mma_bf16(o[ni], pa_h, vh[pi][j0], vh[pi][j0 + 1]);
                }
            }
        }
    }

    const float invA = 1.0f / lAcc;
    const float invB = 1.0f / lBcc;
    const int tA = qi * ABQ + warp * 16 + rA;
    const int tB = tA + 8;
    const size_t baseA = ((size_t)bb * TSEQ + tA) * CDIM + hh * DH;
    const size_t baseB = ((size_t)bb * TSEQ + tB) * CDIM + hh * DH;
#pragma unroll
    for (int ni = 0; ni < 8; ni++) {
        int col = ni * 8 + qcol;
        float yA0 = o[ni][0] * invA, yA1 = o[ni][1] * invA;
        float yB0 = o[ni][2] * invB, yB1 = o[ni][3] * invB;
        __nv_bfloat16 h0, l0, h1, l1;
        __nv_bfloat162 hv, lv;
        bsplit(yA0, h0, l0); bsplit(yA1, h1, l1);
        hv.x = h0; hv.y = h1; lv.x = l0; lv.y = l1;
        *(__nv_bfloat162*)(g_Yhi + baseA + col) = hv;
        *(__nv_bfloat162*)(g_Ylo + baseA + col) = lv;
        bsplit(yB0, h0, l0); bsplit(yB1, h1, l1);
        hv.x = h0; hv.y = h1; lv.x = l0; lv.y = l1;
        *(__nv_bfloat162*)(g_Yhi + baseB + col) = hv;
        *(__nv_bfloat162*)(g_Ylo + baseB + col) = lv;
    }
}

// ---------------------------------------------------------------------------
// Launch
// ---------------------------------------------------------------------------
extern "C" void kernel_launch(void* const* d_in, const int* in_sizes, int n_in,
                              void* d_out, int out_size)
{
    const float* x      = (const float*)d_in[0];
    const float* w_attn = (const float*)d_in[1];
    const float* b_attn = (const float*)d_in[2];
    const float* w_proj = (const float*)d_in[3];
    const float* b_proj = (const float*)d_in[4];
    float* out = (float*)d_out;

    // 0) Fused preprocessing (pure splits, no transpose)
    {
        preproc_kernel<<<8192, 256>>>(x, w_attn, w_proj);
    }

    // 1) QKV GEMM (3xbf16, trans-B, BN=64, 3 CTAs/SM)
    {
        constexpr int GS = 3 * (2 * APANEL + 2 * (32 * 64 * 2));   // 73728
        cudaFuncSetAttribute((const void*)tc_gemm<3 * CDIM, 0, 64, 3>,
                             cudaFuncAttributeMaxDynamicSharedMemorySize, GS);
        dim3 grid(3 * CDIM / 64, MROWS / GBM);    // (48, 32)
        tc_gemm<3 * CDIM, 0, 64, 3><<<grid, 256, GS>>>(b_attn, nullptr);
    }

    // 2) Tensor-core flash attention (3xbf16, single-sync mainloop)
    {
        cudaFuncSetAttribute(attn_kernel,
                             cudaFuncAttributeMaxDynamicSharedMemorySize, ASMEM);
        dim3 grid(TSEQ / ABQ, NB * NH);           // (8, 64)
        attn_kernel<<<grid, 256, ASMEM>>>();
    }

    // 3) Output projection (3xbf16, trans-B, BN=128, 2 CTAs/SM)
    {
        constexpr int GS = 3 * (2 * APANEL + 2 * (32 * 128 * 2));  // 98304
        cudaFuncSetAttribute((const void*)tc_gemm<CDIM, 1, 128, 2>,
                             cudaFuncAttributeMaxDynamicSharedMemorySize, GS);
        dim3 grid(CDIM / 128, MROWS / GBM);       // (8, 32)
        tc_gemm<CDIM, 1, 128, 2><<<grid, 256, GS>>>(b_proj, out);
    }
}

// round 16
// speedup vs baseline: 1.0444x; 1.0444x over previous
#include <cuda_runtime.h>
#include <cuda_bf16.h>
#include <math.h>
#include <stdint.h>

// Problem constants
#define NB    4
#define TSEQ  1024
#define CDIM  1024
#define NH    16
#define DH    64
#define MROWS (NB * TSEQ)      // 4096
#define KDIM  1024

// Scratch (device globals -- no allocation allowed)
__device__ __nv_bfloat16 g_Xhi[(size_t)MROWS * KDIM];
__device__ __nv_bfloat16 g_Xlo[(size_t)MROWS * KDIM];
__device__ __nv_bfloat16 g_Yhi[(size_t)MROWS * KDIM];
__device__ __nv_bfloat16 g_Ylo[(size_t)MROWS * KDIM];
__device__ __nv_bfloat16 g_WAhi[(size_t)KDIM * 3 * CDIM];   // w_attn [k][n] (natural)
__device__ __nv_bfloat16 g_WAlo[(size_t)KDIM * 3 * CDIM];
__device__ __nv_bfloat16 g_WPhi[(size_t)KDIM * CDIM];       // w_proj [k][n] (natural)
__device__ __nv_bfloat16 g_WPlo[(size_t)KDIM * CDIM];
__device__ __nv_bfloat16 g_Qh[(size_t)NB * NH * TSEQ * DH];
__device__ __nv_bfloat16 g_Qlo[(size_t)NB * NH * TSEQ * DH];
__device__ __nv_bfloat16 g_Kh[(size_t)NB * NH * TSEQ * DH];
__device__ __nv_bfloat16 g_Klo[(size_t)NB * NH * TSEQ * DH];
__device__ __nv_bfloat16 g_Vh[(size_t)NB * NH * TSEQ * DH];   // [bh][t][d]
__device__ __nv_bfloat16 g_Vlo[(size_t)NB * NH * TSEQ * DH];

// ---------------------------------------------------------------------------
// Helpers
// ---------------------------------------------------------------------------
__device__ __forceinline__ uint32_t smem_u32(const void* p) {
    return (uint32_t)__cvta_generic_to_shared(p);
}

__device__ __forceinline__ void cp_async16(uint32_t saddr, const void* gptr) {
    asm volatile("cp.async.cg.shared.global [%0], [%1], 16;" :: "r"(saddr), "l"(gptr));
}
#define CP_COMMIT() asm volatile("cp.async.commit_group;" ::: "memory")

__device__ __forceinline__ void ldsm_x4(uint32_t* r, uint32_t addr) {
    asm volatile("ldmatrix.sync.aligned.m8n8.x4.shared.b16 {%0,%1,%2,%3}, [%4];"
                 : "=r"(r[0]), "=r"(r[1]), "=r"(r[2]), "=r"(r[3]) : "r"(addr));
}

__device__ __forceinline__ void ldsm_x4_trans(uint32_t* r, uint32_t addr) {
    asm volatile("ldmatrix.sync.aligned.m8n8.x4.trans.shared.b16 {%0,%1,%2,%3}, [%4];"
                 : "=r"(r[0]), "=r"(r[1]), "=r"(r[2]), "=r"(r[3]) : "r"(addr));
}

__device__ __forceinline__ void mma_bf16(float* c, const uint32_t* a,
                                         uint32_t b0, uint32_t b1) {
    asm volatile(
        "mma.sync.aligned.m16n8k16.row.col.f32.bf16.bf16.f32 "
        "{%0,%1,%2,%3}, {%4,%5,%6,%7}, {%8,%9}, {%0,%1,%2,%3};"
        : "+f"(c[0]), "+f"(c[1]), "+f"(c[2]), "+f"(c[3])
        : "r"(a[0]), "r"(a[1]), "r"(a[2]), "r"(a[3]), "r"(b0), "r"(b1));
}

__device__ __forceinline__ void bsplit(float f, __nv_bfloat16& h, __nv_bfloat16& l) {
    h = __float2bfloat16_rn(f);
    l = __float2bfloat16_rn(f - __bfloat162float(h));
}

__device__ __forceinline__ float fast_exp2(float x) {
    float r;
    asm("ex2.approx.ftz.f32 %0, %1;" : "=f"(r) : "f"(x));
    return r;
}

// ---------------------------------------------------------------------------
// Fused preprocessing: pure elementwise bf16 split (NO transposes).
// ---------------------------------------------------------------------------
__device__ __forceinline__ void split4(const float* __restrict__ s,
        __nv_bfloat16* dh, __nv_bfloat16* dl, size_t i)
{
    float4 v = *(const float4*)(s + i);
    __nv_bfloat16 h0, l0, h1, l1, h2, l2, h3, l3;
    bsplit(v.x, h0, l0); bsplit(v.y, h1, l1);
    bsplit(v.z, h2, l2); bsplit(v.w, h3, l3);
    __nv_bfloat162* ph = (__nv_bfloat162*)(dh + i);
    __nv_bfloat162* pl = (__nv_bfloat162*)(dl + i);
    __nv_bfloat162 a; a.x = h0; a.y = h1;
    __nv_bfloat162 b; b.x = h2; b.y = h3;
    ph[0] = a; ph[1] = b;
    a.x = l0; a.y = l1; b.x = l2; b.y = l3;
    pl[0] = a; pl[1] = b;
}

__global__ __launch_bounds__(256) void preproc_kernel(const float* __restrict__ x,
        const float* __restrict__ wa, const float* __restrict__ wp)
{
    const int bid = blockIdx.x;
    const int tid = threadIdx.x;
    if (bid < 3072) {
        size_t i = ((size_t)bid * 256 + tid) * 4;
        split4(wa, g_WAhi, g_WAlo, i);
    } else if (bid < 4096) {
        size_t i = ((size_t)(bid - 3072) * 256 + tid) * 4;
        split4(wp, g_WPhi, g_WPlo, i);
    } else {
        size_t i = ((size_t)(bid - 4096) * 256 + tid) * 4;
        split4(x, g_Xhi, g_Xlo, i);
    }
}

// ---------------------------------------------------------------------------
// 3xBF16 mma.sync GEMM, BN templated.
// BN=64:  stage 24K, 3 stages = 72K  -> 3 CTAs/SM (QKV, measured best)
// BN=128: stage 32K, 3 stages = 96K  -> 2 CTAs/SM (proj, measured best)
// A: [m][k] hi/lo; B: natural [k][n] hi/lo via ldmatrix.trans.
// ---------------------------------------------------------------------------
#define GBM 128
#define GBK 32
#define KTILES  (KDIM / GBK)            // 32
#define APANEL  8192                     // 128r x 64B

__device__ __forceinline__ uint32_t sw64(int row, int ch) {
    return (uint32_t)row * 64 + (uint32_t)((ch ^ ((row >> 1) & 3)) << 4);
}
template <int BN>
__device__ __forceinline__ uint32_t swB(int row, int ch) {
    return (uint32_t)row * (BN * 2) + (uint32_t)((ch ^ (row & (BN / 8 - 1))) << 4);
}

template <int N, int BN>
__device__ __forceinline__ void load_tile_b(uint32_t sg,
        const __nv_bfloat16* Ah, const __nv_bfloat16* Al,
        const __nv_bfloat16* Bh, const __nv_bfloat16* Bl,
        int k0, int tid)
{
    constexpr int NCH = BN / 8;
    constexpr int BPANEL = 32 * BN * 2;
    constexpr int OBH = 2 * APANEL;
    constexpr int OBL = OBH + BPANEL;
    constexpr int TOT = 1024 + 2 * 32 * NCH;
#pragma unroll
    for (int l = 0; l < TOT / 256; l++) {
        int idx = tid + l * 256;
        if (idx < 1024) {
            int panel = idx >> 9;
            int rem = idx & 511;
            int row = rem >> 2;
            int ch  = rem & 3;
            cp_async16(sg + (panel ? APANEL : 0) + sw64(row, ch),
                       (panel ? Al : Ah) + (size_t)row * KDIM + k0 + ch * 8);
        } else {
            int rem = idx - 1024;
            int panel = rem / (32 * NCH);
            int rem2 = rem % (32 * NCH);
            int row = rem2 / NCH;
            int ch  = rem2 % NCH;
            cp_async16(sg + (panel ? OBL : OBH) + swB<BN>(row, ch),
                       (panel ? Bl : Bh) + (size_t)(k0 + row) * N + ch * 8);
        }
    }
}

template <int N, int MODE, int BN, int MINCTAS>
__global__ __launch_bounds__(256, MINCTAS) void tc_gemm(const float* __restrict__ bias,
                                                        float* __restrict__ out)
{
    constexpr int BPANEL = 32 * BN * 2;
    constexpr int STAGE = 2 * APANEL + 2 * BPANEL;
    constexpr int OBH = 2 * APANEL;
    constexpr int OBL = OBH + BPANEL;
    constexpr int NPW = (BN / 2) / 8;

    extern __shared__ char smem[];
    const uint32_t sbase = smem_u32(smem);
    const int tid  = threadIdx.x;
    const int warp = tid >> 5;
    const int lane = tid & 31;
    const int wm = warp >> 1;
    const int wn = warp & 1;
    const int bm = blockIdx.y * GBM;
    const int bn = blockIdx.x * BN;

    const __nv_bfloat16* Ah = ((MODE == 0) ? g_Xhi : g_Yhi) + (size_t)bm * KDIM;
    const __nv_bfloat16* Al = ((MODE == 0) ? g_Xlo : g_Ylo) + (size_t)bm * KDIM;
    const __nv_bfloat16* Bh = ((MODE == 0) ? g_WAhi : g_WPhi) + bn;
    const __nv_bfloat16* Bl = ((MODE == 0) ? g_WAlo : g_WPlo) + bn;

    const int arow = wm * 32 + (lane & 15);
    const int acb = (lane >> 4) & 1;
    const int koffG = (((lane >> 3) & 1) << 3) + (lane & 7);
    const int noctG = lane >> 4;

    float acc[2][NPW][4];
#pragma unroll
    for (int mi = 0; mi < 2; mi++)
#pragma unroll
        for (int ni = 0; ni < NPW; ni++)
#pragma unroll
            for (int r = 0; r < 4; r++) acc[mi][ni][r] = 0.0f;

#pragma unroll
    for (int t = 0; t < 2; t++) {
        load_tile_b<N, BN>(sbase + t * STAGE, Ah, Al, Bh, Bl, t * GBK, tid);
        CP_COMMIT();
    }

    for (int t = 0; t < KTILES; t++) {
        if (t < KTILES - 2)
            asm volatile("cp.async.wait_group 1;" ::: "memory");
        else
            asm volatile("cp.async.wait_group 0;" ::: "memory");
        __syncthreads();

        const uint32_t sg = sbase + (uint32_t)(t % 3) * STAGE;

#pragma unroll
        for (int ks = 0; ks < 2; ks++) {
            uint32_t ah[2][4], al[2][4];
#pragma unroll
            for (int mi = 0; mi < 2; mi++) {
                uint32_t ao = sw64(arow + mi * 16, ks * 2 + acb);
                ldsm_x4(ah[mi], sg + 0 + ao);
                ldsm_x4(al[mi], sg + APANEL + ao);
            }
#pragma unroll
            for (int pi = 0; pi < NPW / 2; pi++) {
                uint32_t bh[4], bl[4];
                int vr = ks * 16 + koffG;
                int chv = wn * NPW + 2 * pi + noctG;
                uint32_t bo = swB<BN>(vr, chv);
                ldsm_x4_trans(bh, sg + OBH + bo);
                ldsm_x4_trans(bl, sg + OBL + bo);
#pragma unroll
                for (int mi = 0; mi < 2; mi++)
#pragma unroll
                    for (int sub = 0; sub < 2; sub++) {
                        const int ni = pi * 2 + sub;
                        const int j0 = sub * 2;
                        mma_bf16(acc[mi][ni], al[mi], bh[j0], bh[j0 + 1]);
                        mma_bf16(acc[mi][ni], ah[mi], bl[j0], bl[j0 + 1]);
                        mma_bf16(acc[mi][ni], ah[mi], bh[j0], bh[j0 + 1]);
                    }
            }
        }

        if (t + 2 < KTILES) {
            load_tile_b<N, BN>(sbase + (uint32_t)((t + 2) % 3) * STAGE,
                               Ah, Al, Bh, Bl, (t + 2) * GBK, tid);
            CP_COMMIT();
        }
    }

    // Epilogue
#pragma unroll
    for (int mi = 0; mi < 2; mi++) {
#pragma unroll
        for (int ni = 0; ni < NPW; ni++) {
            const int col = bn + wn * (BN / 2) + ni * 8 + (lane & 3) * 2;
            float2 bv = *(const float2*)(bias + col);
#pragma unroll
            for (int half = 0; half < 2; half++) {
                const int row = bm + wm * 32 + mi * 16 + (lane >> 2) + half * 8;
                float vx = acc[mi][ni][half * 2 + 0] + bv.x;
                float vy = acc[mi][ni][half * 2 + 1] + bv.y;
                if (MODE == 0) {
                    const int sec  = col >> 10;          // 0=q, 1=k, 2=v
                    const int cc   = col & 1023;
                    const int head = cc >> 6;
                    const int dpos = cc & 63;
                    const int b  = row >> 10;
                    const int tt = row & 1023;
                    const int bh2 = b * NH + head;
                    __nv_bfloat16 hx, lx, hy, ly;
                    bsplit(vx, hx, lx); bsplit(vy, hy, ly);
                    __nv_bfloat16* dh = (sec == 0) ? g_Qh : (sec == 1) ? g_Kh : g_Vh;
                    __nv_bfloat16* dl = (sec == 0) ? g_Qlo : (sec == 1) ? g_Klo : g_Vlo;
                    size_t o = ((size_t)bh2 * TSEQ + tt) * DH + dpos;
                    __nv_bfloat162 hv; hv.x = hx; hv.y = hy;
                    __nv_bfloat162 lv; lv.x = lx; lv.y = ly;
                    *(__nv_bfloat162*)(dh + o) = hv;
                    *(__nv_bfloat162*)(dl + o) = lv;
                } else {
                    float2 v2; v2.x = vx; v2.y = vy;
                    *(float2*)(out + (size_t)row * N + col) = v2;
                }
            }
        }
    }
}

// ---------------------------------------------------------------------------
// Tensor-core flash attention, 3xBF16, register-resident P, double-buffered
// K/V, trans-ldmatrix V. EXACT R14 two-sync mainloop (measured best):
// prefetch issue -> commit -> wait_group 1 -> sync -> compute -> sync.
// ---------------------------------------------------------------------------
#define ABQ   128
#define ABK   64
#define SQH 0
#define SQL 16384
#define SKV 32768
#define ASMEM 98304

__device__ __forceinline__ void attn_load_kv(uint32_t sbuf,
        const __nv_bfloat16* Khp, const __nv_bfloat16* Klp,
        const __nv_bfloat16* Vhp, const __nv_bfloat16* Vlp,
        int k0, int tid)
{
#pragma unroll
    for (int l = 0; l < 4; l++) {
        int idx = tid + l * 256;
        int panel = idx >> 9;
        int rem = idx & 511;
        int r = rem >> 3, ch = rem & 7;
        uint32_t off = (uint32_t)r * 128 + ch * 16;
        uint32_t sw = off ^ ((off >> 3) & 0x70);
        cp_async16(sbuf + (panel ? 8192 : 0) + sw,
                   (panel ? Klp : Khp) + (size_t)(k0 + r) * DH + ch * 8);
        cp_async16(sbuf + (panel ? 24576 : 16384) + sw,
                   (panel ? Vlp : Vhp) + (size_t)(k0 + r) * DH + ch * 8);
    }
}

__global__ __launch_bounds__(256, 2) void attn_kernel()
{
    extern __shared__ char smc[];
    const uint32_t sb = smem_u32(smc);

    const int qi = gridDim.x - 1 - blockIdx.x;
    const int bh = blockIdx.y;
    const int bb = bh >> 4, hh = bh & 15;
    const __nv_bfloat16* Qhp = g_Qh  + (size_t)bh * TSEQ * DH;
    const __nv_bfloat16* Qlp = g_Qlo + (size_t)bh * TSEQ * DH;
    const __nv_bfloat16* Khp = g_Kh  + (size_t)bh * TSEQ * DH;
    const __nv_bfloat16* Klp = g_Klo + (size_t)bh * TSEQ * DH;
    const __nv_bfloat16* Vhp = g_Vh  + (size_t)bh * TSEQ * DH;
    const __nv_bfloat16* Vlp = g_Vlo + (size_t)bh * TSEQ * DH;

    const int tid  = threadIdx.x;
    const int warp = tid >> 5;
    const int lane = tid & 31;
    const int rA   = lane >> 2;
    const int qcol = (lane & 3) * 2;

    const int acb  = (lane >> 4) & 1;
    const int bcb  = (lane >> 3) & 1;
    const int brow = (lane & 7) + ((lane & 16) >> 1);
    const int koff = (((lane >> 3) & 1) << 3) + (lane & 7);
    const int noct = lane >> 4;

#pragma unroll
    for (int l = 0; l < 8; l++) {
        int idx = tid + l * 256;
        int panel = idx >> 10;
        int rem = idx & 1023;
        int r = rem >> 3, ch = rem & 7;
        uint32_t off = (uint32_t)r * 128 + ch * 16;
        uint32_t sw = off ^ ((off >> 3) & 0x70);
        const __nv_bfloat16* src = (panel ? Qlp : Qhp) + (size_t)(qi * ABQ + r) * DH + ch * 8;
        cp_async16(sb + (panel ? SQL : SQH) + sw, src);
    }
    attn_load_kv(sb + SKV, Khp, Klp, Vhp, Vlp, 0, tid);
    CP_COMMIT();

    float o[8][4];
#pragma unroll
    for (int ni = 0; ni < 8; ni++)
#pragma unroll
        for (int j = 0; j < 4; j++) o[ni][j] = 0.0f;
    float mA = -1e30f, mB = -1e30f, lAcc = 0.0f, lBcc = 0.0f;

    const float CS = 0.18033688011112042f;
    const int ntiles = 2 * qi + 2;

    for (int kt = 0; kt < ntiles; kt++) {
        if (kt + 1 < ntiles) {
            attn_load_kv(sb + SKV + ((kt + 1) & 1) * 32768,
                         Khp, Klp, Vhp, Vlp, (kt + 1) * ABK, tid);
            CP_COMMIT();
            asm volatile("cp.async.wait_group 1;" ::: "memory");
        } else {
            asm volatile("cp.async.wait_group 0;" ::: "memory");
        }
        __syncthreads();

        const uint32_t skv = sb + SKV + (uint32_t)(kt & 1) * 32768;

        if (kt * ABK <= qi * ABQ + warp * 16 + 15) {
            float s[8][4];
#pragma unroll
            for (int ni = 0; ni < 8; ni++)
#pragma unroll
                for (int j = 0; j < 4; j++) s[ni][j] = 0.0f;

            const int aQrow = warp * 16 + (lane & 15);
            const uint32_t a_ro = (uint32_t)aQrow * 128;
            const int a_rx = aQrow & 7;
#pragma unroll
            for (int ks = 0; ks < 4; ks++) {
                uint32_t ah[4], al[4], kh[4][4], kl[4][4];
                uint32_t ao = a_ro + (uint32_t)(((ks * 2 + acb) ^ a_rx) << 4);
                ldsm_x4(ah, sb + SQH + ao);
                ldsm_x4(al, sb + SQL + ao);
#pragma unroll
                for (int pi = 0; pi < 4; pi++) {
                    int br = pi * 16 + brow;
                    uint32_t bo = (uint32_t)br * 128 +
                                  (uint32_t)(((ks * 2 + bcb) ^ (br & 7)) << 4);
                    ldsm_x4(kh[pi], skv + bo);
                    ldsm_x4(kl[pi], skv + 8192 + bo);
                }
#pragma unroll
                for (int ni = 0; ni < 8; ni++) {
                    const int pi = ni >> 1, j0 = (ni & 1) * 2;
                    mma_bf16(s[ni], al, kh[pi][j0], kh[pi][j0 + 1]);
                    mma_bf16(s[ni], ah, kl[pi][j0], kl[pi][j0 + 1]);
                    mma_bf16(s[ni], ah, kh[pi][j0], kh[pi][j0 + 1]);
                }
            }

            const bool needmask = (kt * ABK + ABK - 1 > qi * ABQ + warp * 16);
            const int rowgA = qi * ABQ + warp * 16 + rA;
            const int rowgB = rowgA + 8;
            const int cb = kt * ABK + qcol;
#pragma unroll
            for (int ni = 0; ni < 8; ni++) {
                float z0 = s[ni][0] * CS, z1 = s[ni][1] * CS;
                float z2 = s[ni][2] * CS, z3 = s[ni][3] * CS;
                if (needmask) {
                    int c0 = cb + ni * 8, c1 = c0 + 1;
                    if (c0 > rowgA) z0 = -1e30f;
                    if (c1 > rowgA) z1 = -1e30f;
                    if (c0 > rowgB) z2 = -1e30f;
                    if (c1 > rowgB) z3 = -1e30f;
                }
                s[ni][0] = z0; s[ni][1] = z1; s[ni][2] = z2; s[ni][3] = z3;
            }

            float mtA = -1e30f, mtB = -1e30f;
#pragma unroll
            for (int ni = 0; ni < 8; ni++) {
                mtA = fmaxf(mtA, fmaxf(s[ni][0], s[ni][1]));
                mtB = fmaxf(mtB, fmaxf(s[ni][2], s[ni][3]));
            }
            mtA = fmaxf(mtA, __shfl_xor_sync(0xffffffffu, mtA, 1));
            mtA = fmaxf(mtA, __shfl_xor_sync(0xffffffffu, mtA, 2));
            mtB = fmaxf(mtB, __shfl_xor_sync(0xffffffffu, mtB, 1));
            mtB = fmaxf(mtB, __shfl_xor_sync(0xffffffffu, mtB, 2));

            const float mnA = fmaxf(mA, mtA);
            const float mnB = fmaxf(mB, mtB);
            const float aAl = fast_exp2(mA - mnA);
            const float aBl = fast_exp2(mB - mnB);
            mA = mnA; mB = mnB;

            float psA = 0.0f, psB = 0.0f;
#pragma unroll
            for (int ni = 0; ni < 8; ni++) {
                float p0 = fast_exp2(s[ni][0] - mnA);
                float p1 = fast_exp2(s[ni][1] - mnA);
                float p2 = fast_exp2(s[ni][2] - mnB);
                float p3 = fast_exp2(s[ni][3] - mnB);
                psA += p0 + p1; psB += p2 + p3;
                s[ni][0] = p0; s[ni][1] = p1; s[ni][2] = p2; s[ni][3] = p3;
            }
            psA += __shfl_xor_sync(0xffffffffu, psA, 1);
            psA += __shfl_xor_sync(0xffffffffu, psA, 2);
            psB += __shfl_xor_sync(0xffffffffu, psB, 1);
            psB += __shfl_xor_sync(0xffffffffu, psB, 2);
            lAcc = lAcc * aAl + psA;
            lBcc = lBcc * aBl + psB;

#pragma unroll
            for (int ni = 0; ni < 8; ni++) {
                o[ni][0] *= aAl; o[ni][1] *= aAl;
                o[ni][2] *= aBl; o[ni][3] *= aBl;
            }

#pragma unroll
            for (int j = 0; j < 4; j++) {
                uint32_t pa_h[4], pa_l[4];
#pragma unroll
                for (int half = 0; half < 2; half++) {
                    const float* sp = s[2 * j + half];
                    __nv_bfloat162 h0 = __floats2bfloat162_rn(sp[0], sp[1]);
                    __nv_bfloat162 h1 = __floats2bfloat162_rn(sp[2], sp[3]);
                    __nv_bfloat162 l0 = __floats2bfloat162_rn(
                        sp[0] - __bfloat162float(h0.x), sp[1] - __bfloat162float(h0.y));
                    __nv_bfloat162 l1 = __floats2bfloat162_rn(
                        sp[2] - __bfloat162float(h1.x), sp[3] - __bfloat162float(h1.y));
                    pa_h[half * 2 + 0] = *(uint32_t*)&h0;
                    pa_h[half * 2 + 1] = *(uint32_t*)&h1;
                    pa_l[half * 2 + 0] = *(uint32_t*)&l0;
                    pa_l[half * 2 + 1] = *(uint32_t*)&l1;
                }

                uint32_t vh[4][4], vl[4][4];
                const int vrow = j * 16 + koff;
                const uint32_t vro = (uint32_t)vrow * 128;
                const int v_rx = vrow & 7;
#pragma unroll
                for (int pi = 0; pi < 4; pi++) {
                    uint32_t chv = (uint32_t)(2 * pi + noct);
                    uint32_t bo = vro + ((chv ^ (uint32_t)v_rx) << 4);
                    ldsm_x4_trans(vh[pi], skv + 16384 + bo);
                    ldsm_x4_trans(vl[pi], skv + 24576 + bo);
                }
#pragma unroll
                for (int ni = 0; ni < 8; ni++) {
                    const int pi = ni >> 1, j0 = (ni & 1) * 2;
                    mma_bf16(o[ni], pa_l, vh[pi][j0], vh[pi][j0 + 1]);
                    mma_bf16(o[ni], pa_h, vl[pi][j0], vl[pi][j0 + 1]);
                    mma_bf16(o[ni], pa_h, vh[pi][j0], vh[pi][j0 + 1]);
                }
            }
        }
        __syncthreads();
    }

    const float invA = 1.0f / lAcc;
    const float invB = 1.0f / lBcc;
    const int tA = qi * ABQ + warp * 16 + rA;
    const int tB = tA + 8;
    const size_t baseA = ((size_t)bb * TSEQ + tA) * CDIM + hh * DH;
    const size_t baseB = ((size_t)bb * TSEQ + tB) * CDIM + hh * DH;
#pragma unroll
    for (int ni = 0; ni < 8; ni++) {
        int col = ni * 8 + qcol;
        float yA0 = o[ni][0] * invA, yA1 = o[ni][1] * invA;
        float yB0 = o[ni][2] * invB, yB1 = o[ni][3] * invB;
        __nv_bfloat16 h0, l0, h1, l1;
        __nv_bfloat162 hv, lv;
        bsplit(yA0, h0, l0); bsplit(yA1, h1, l1);
        hv.x = h0; hv.y = h1; lv.x = l0; lv.y = l1;
        *(__nv_bfloat162*)(g_Yhi + baseA + col) = hv;
        *(__nv_bfloat162*)(g_Ylo + baseA + col) = lv;
        bsplit(yB0, h0, l0); bsplit(yB1, h1, l1);
        hv.x = h0; hv.y = h1; lv.x = l0; lv.y = l1;
        *(__nv_bfloat162*)(g_Yhi + baseB + col) = hv;
        *(__nv_bfloat162*)(g_Ylo + baseB + col) = lv;
    }
}

// ---------------------------------------------------------------------------
// Launch
// ---------------------------------------------------------------------------
extern "C" void kernel_launch(void* const* d_in, const int* in_sizes, int n_in,
                              void* d_out, int out_size)
{
    const float* x      = (const float*)d_in[0];
    const float* w_attn = (const float*)d_in[1];
    const float* b_attn = (const float*)d_in[2];
    const float* w_proj = (const float*)d_in[3];
    const float* b_proj = (const float*)d_in[4];
    float* out = (float*)d_out;

    // 0) Fused preprocessing (pure splits, no transpose)
    {
        preproc_kernel<<<8192, 256>>>(x, w_attn, w_proj);
    }

    // 1) QKV GEMM (3xbf16, trans-B, BN=64, 3 CTAs/SM)
    {
        constexpr int GS = 3 * (2 * APANEL + 2 * (32 * 64 * 2));   // 73728
        cudaFuncSetAttribute(tc_gemm<3 * CDIM, 0, 64, 3>,
                             cudaFuncAttributeMaxDynamicSharedMemorySize, GS);
        dim3 grid(3 * CDIM / 64, MROWS / GBM);    // (48, 32)
        tc_gemm<3 * CDIM, 0, 64, 3><<<grid, 256, GS>>>(b_attn, nullptr);
    }

    // 2) Tensor-core flash attention (3xbf16, R14 two-sync mainloop)
    {
        cudaFuncSetAttribute(attn_kernel,
                             cudaFuncAttributeMaxDynamicSharedMemorySize, ASMEM);
        dim3 grid(TSEQ / ABQ, NB * NH);           // (8, 64)
        attn_kernel<<<grid, 256, ASMEM>>>();
    }

    // 3) Output projection (3xbf16, trans-B, BN=128, 2 CTAs/SM)
    {
        constexpr int GS = 3 * (2 * APANEL + 2 * (32 * 128 * 2));  // 98304
        cudaFuncSetAttribute(tc_gemm<CDIM, 1, 128, 2>,
                             cudaFuncAttributeMaxDynamicSharedMemorySize, GS);
        dim3 grid(CDIM / 128, MROWS / GBM);       // (8, 32)
        tc_gemm<CDIM, 1, 128, 2><<<grid, 256, GS>>>(b_proj, out);
    }
}

// round 17
// speedup vs baseline: 1.1281x; 1.0801x over previous
#include <cuda_runtime.h>
#include <cuda_bf16.h>
#include <math.h>
#include <stdint.h>

// Problem constants
#define NB    4
#define TSEQ  1024
#define CDIM  1024
#define NH    16
#define DH    64
#define MROWS (NB * TSEQ)      // 4096
#define KDIM  1024

// Scratch (device globals -- no allocation allowed)
__device__ __nv_bfloat16 g_Xhi[(size_t)MROWS * KDIM];
__device__ __nv_bfloat16 g_Xlo[(size_t)MROWS * KDIM];
__device__ __nv_bfloat16 g_Yhi[(size_t)MROWS * KDIM];
__device__ __nv_bfloat16 g_Ylo[(size_t)MROWS * KDIM];
__device__ __nv_bfloat16 g_WAhi[(size_t)KDIM * 3 * CDIM];   // w_attn [k][n] (natural)
__device__ __nv_bfloat16 g_WAlo[(size_t)KDIM * 3 * CDIM];
__device__ __nv_bfloat16 g_WPhi[(size_t)KDIM * CDIM];       // w_proj [k][n] (natural)
__device__ __nv_bfloat16 g_WPlo[(size_t)KDIM * CDIM];
__device__ __nv_bfloat16 g_Qh[(size_t)NB * NH * TSEQ * DH];
__device__ __nv_bfloat16 g_Qlo[(size_t)NB * NH * TSEQ * DH];
__device__ __nv_bfloat16 g_Kh[(size_t)NB * NH * TSEQ * DH];
__device__ __nv_bfloat16 g_Klo[(size_t)NB * NH * TSEQ * DH];
__device__ __nv_bfloat16 g_Vh[(size_t)NB * NH * TSEQ * DH];   // [bh][t][d]
__device__ __nv_bfloat16 g_Vlo[(size_t)NB * NH * TSEQ * DH];

// ---------------------------------------------------------------------------
// Helpers
// ---------------------------------------------------------------------------
__device__ __forceinline__ uint32_t smem_u32(const void* p) {
    return (uint32_t)__cvta_generic_to_shared(p);
}

__device__ __forceinline__ void cp_async16(uint32_t saddr, const void* gptr) {
    asm volatile("cp.async.cg.shared.global [%0], [%1], 16;" :: "r"(saddr), "l"(gptr));
}
#define CP_COMMIT() asm volatile("cp.async.commit_group;" ::: "memory")

__device__ __forceinline__ void ldsm_x4(uint32_t* r, uint32_t addr) {
    asm volatile("ldmatrix.sync.aligned.m8n8.x4.shared.b16 {%0,%1,%2,%3}, [%4];"
                 : "=r"(r[0]), "=r"(r[1]), "=r"(r[2]), "=r"(r[3]) : "r"(addr));
}

__device__ __forceinline__ void ldsm_x4_trans(uint32_t* r, uint32_t addr) {
    asm volatile("ldmatrix.sync.aligned.m8n8.x4.trans.shared.b16 {%0,%1,%2,%3}, [%4];"
                 : "=r"(r[0]), "=r"(r[1]), "=r"(r[2]), "=r"(r[3]) : "r"(addr));
}

__device__ __forceinline__ void mma_bf16(float* c, const uint32_t* a,
                                         uint32_t b0, uint32_t b1) {
    asm volatile(
        "mma.sync.aligned.m16n8k16.row.col.f32.bf16.bf16.f32 "
        "{%0,%1,%2,%3}, {%4,%5,%6,%7}, {%8,%9}, {%0,%1,%2,%3};"
        : "+f"(c[0]), "+f"(c[1]), "+f"(c[2]), "+f"(c[3])
        : "r"(a[0]), "r"(a[1]), "r"(a[2]), "r"(a[3]), "r"(b0), "r"(b1));
}

__device__ __forceinline__ void bsplit(float f, __nv_bfloat16& h, __nv_bfloat16& l) {
    h = __float2bfloat16_rn(f);
    l = __float2bfloat16_rn(f - __bfloat162float(h));
}

__device__ __forceinline__ float fast_exp2(float x) {
    float r;
    asm("ex2.approx.ftz.f32 %0, %1;" : "=f"(r) : "f"(x));
    return r;
}

// ---------------------------------------------------------------------------
// Fused preprocessing: pure elementwise bf16 split (NO transposes).
// ---------------------------------------------------------------------------
__device__ __forceinline__ void split4(const float* __restrict__ s,
        __nv_bfloat16* dh, __nv_bfloat16* dl, size_t i)
{
    float4 v = *(const float4*)(s + i);
    __nv_bfloat16 h0, l0, h1, l1, h2, l2, h3, l3;
    bsplit(v.x, h0, l0); bsplit(v.y, h1, l1);
    bsplit(v.z, h2, l2); bsplit(v.w, h3, l3);
    __nv_bfloat162* ph = (__nv_bfloat162*)(dh + i);
    __nv_bfloat162* pl = (__nv_bfloat162*)(dl + i);
    __nv_bfloat162 a; a.x = h0; a.y = h1;
    __nv_bfloat162 b; b.x = h2; b.y = h3;
    ph[0] = a; ph[1] = b;
    a.x = l0; a.y = l1; b.x = l2; b.y = l3;
    pl[0] = a; pl[1] = b;
}

__global__ __launch_bounds__(256) void preproc_kernel(const float* __restrict__ x,
        const float* __restrict__ wa, const float* __restrict__ wp)
{
    const int bid = blockIdx.x;
    const int tid = threadIdx.x;
    if (bid < 3072) {
        size_t i = ((size_t)bid * 256 + tid) * 4;
        split4(wa, g_WAhi, g_WAlo, i);
    } else if (bid < 4096) {
        size_t i = ((size_t)(bid - 3072) * 256 + tid) * 4;
        split4(wp, g_WPhi, g_WPlo, i);
    } else {
        size_t i = ((size_t)(bid - 4096) * 256 + tid) * 4;
        split4(x, g_Xhi, g_Xlo, i);
    }
}

// ---------------------------------------------------------------------------
// 3xBF16 mma.sync GEMM, BN templated. (unchanged from R16)
// BN=64:  3 CTAs/SM (QKV).  BN=128: 2 CTAs/SM (proj).
// ---------------------------------------------------------------------------
#define GBM 128
#define GBK 32
#define KTILES  (KDIM / GBK)            // 32
#define APANEL  8192                     // 128r x 64B

__device__ __forceinline__ uint32_t sw64(int row, int ch) {
    return (uint32_t)row * 64 + (uint32_t)((ch ^ ((row >> 1) & 3)) << 4);
}
template <int BN>
__device__ __forceinline__ uint32_t swB(int row, int ch) {
    return (uint32_t)row * (BN * 2) + (uint32_t)((ch ^ (row & (BN / 8 - 1))) << 4);
}

template <int N, int BN>
__device__ __forceinline__ void load_tile_b(uint32_t sg,
        const __nv_bfloat16* Ah, const __nv_bfloat16* Al,
        const __nv_bfloat16* Bh, const __nv_bfloat16* Bl,
        int k0, int tid)
{
    constexpr int NCH = BN / 8;
    constexpr int BPANEL = 32 * BN * 2;
    constexpr int OBH = 2 * APANEL;
    constexpr int OBL = OBH + BPANEL;
    constexpr int TOT = 1024 + 2 * 32 * NCH;
#pragma unroll
    for (int l = 0; l < TOT / 256; l++) {
        int idx = tid + l * 256;
        if (idx < 1024) {
            int panel = idx >> 9;
            int rem = idx & 511;
            int row = rem >> 2;
            int ch  = rem & 3;
            cp_async16(sg + (panel ? APANEL : 0) + sw64(row, ch),
                       (panel ? Al : Ah) + (size_t)row * KDIM + k0 + ch * 8);
        } else {
            int rem = idx - 1024;
            int panel = rem / (32 * NCH);
            int rem2 = rem % (32 * NCH);
            int row = rem2 / NCH;
            int ch  = rem2 % NCH;
            cp_async16(sg + (panel ? OBL : OBH) + swB<BN>(row, ch),
                       (panel ? Bl : Bh) + (size_t)(k0 + row) * N + ch * 8);
        }
    }
}

template <int N, int MODE, int BN, int MINCTAS>
__global__ __launch_bounds__(256, MINCTAS) void tc_gemm(const float* __restrict__ bias,
                                                        float* __restrict__ out)
{
    constexpr int BPANEL = 32 * BN * 2;
    constexpr int STAGE = 2 * APANEL + 2 * BPANEL;
    constexpr int OBH = 2 * APANEL;
    constexpr int OBL = OBH + BPANEL;
    constexpr int NPW = (BN / 2) / 8;

    extern __shared__ char smem[];
    const uint32_t sbase = smem_u32(smem);
    const int tid  = threadIdx.x;
    const int warp = tid >> 5;
    const int lane = tid & 31;
    const int wm = warp >> 1;
    const int wn = warp & 1;
    const int bm = blockIdx.y * GBM;
    const int bn = blockIdx.x * BN;

    const __nv_bfloat16* Ah = ((MODE == 0) ? g_Xhi : g_Yhi) + (size_t)bm * KDIM;
    const __nv_bfloat16* Al = ((MODE == 0) ? g_Xlo : g_Ylo) + (size_t)bm * KDIM;
    const __nv_bfloat16* Bh = ((MODE == 0) ? g_WAhi : g_WPhi) + bn;
    const __nv_bfloat16* Bl = ((MODE == 0) ? g_WAlo : g_WPlo) + bn;

    const int arow = wm * 32 + (lane & 15);
    const int acb = (lane >> 4) & 1;
    const int koffG = (((lane >> 3) & 1) << 3) + (lane & 7);
    const int noctG = lane >> 4;

    float acc[2][NPW][4];
#pragma unroll
    for (int mi = 0; mi < 2; mi++)
#pragma unroll
        for (int ni = 0; ni < NPW; ni++)
#pragma unroll
            for (int r = 0; r < 4; r++) acc[mi][ni][r] = 0.0f;

#pragma unroll
    for (int t = 0; t < 2; t++) {
        load_tile_b<N, BN>(sbase + t * STAGE, Ah, Al, Bh, Bl, t * GBK, tid);
        CP_COMMIT();
    }

    for (int t = 0; t < KTILES; t++) {
        if (t < KTILES - 2)
            asm volatile("cp.async.wait_group 1;" ::: "memory");
        else
            asm volatile("cp.async.wait_group 0;" ::: "memory");
        __syncthreads();

        const uint32_t sg = sbase + (uint32_t)(t % 3) * STAGE;

#pragma unroll
        for (int ks = 0; ks < 2; ks++) {
            uint32_t ah[2][4], al[2][4];
#pragma unroll
            for (int mi = 0; mi < 2; mi++) {
                uint32_t ao = sw64(arow + mi * 16, ks * 2 + acb);
                ldsm_x4(ah[mi], sg + 0 + ao);
                ldsm_x4(al[mi], sg + APANEL + ao);
            }
#pragma unroll
            for (int pi = 0; pi < NPW / 2; pi++) {
                uint32_t bh[4], bl[4];
                int vr = ks * 16 + koffG;
                int chv = wn * NPW + 2 * pi + noctG;
                uint32_t bo = swB<BN>(vr, chv);
                ldsm_x4_trans(bh, sg + OBH + bo);
                ldsm_x4_trans(bl, sg + OBL + bo);
#pragma unroll
                for (int mi = 0; mi < 2; mi++)
#pragma unroll
                    for (int sub = 0; sub < 2; sub++) {
                        const int ni = pi * 2 + sub;
                        const int j0 = sub * 2;
                        mma_bf16(acc[mi][ni], al[mi], bh[j0], bh[j0 + 1]);
                        mma_bf16(acc[mi][ni], ah[mi], bl[j0], bl[j0 + 1]);
                        mma_bf16(acc[mi][ni], ah[mi], bh[j0], bh[j0 + 1]);
                    }
            }
        }

        if (t + 2 < KTILES) {
            load_tile_b<N, BN>(sbase + (uint32_t)((t + 2) % 3) * STAGE,
                               Ah, Al, Bh, Bl, (t + 2) * GBK, tid);
            CP_COMMIT();
        }
    }

    // Epilogue
#pragma unroll
    for (int mi = 0; mi < 2; mi++) {
#pragma unroll
        for (int ni = 0; ni < NPW; ni++) {
            const int col = bn + wn * (BN / 2) + ni * 8 + (lane & 3) * 2;
            float2 bv = *(const float2*)(bias + col);
#pragma unroll
            for (int half = 0; half < 2; half++) {
                const int row = bm + wm * 32 + mi * 16 + (lane >> 2) + half * 8;
                float vx = acc[mi][ni][half * 2 + 0] + bv.x;
                float vy = acc[mi][ni][half * 2 + 1] + bv.y;
                if (MODE == 0) {
                    const int sec  = col >> 10;          // 0=q, 1=k, 2=v
                    const int cc   = col & 1023;
                    const int head = cc >> 6;
                    const int dpos = cc & 63;
                    const int b  = row >> 10;
                    const int tt = row & 1023;
                    const int bh2 = b * NH + head;
                    __nv_bfloat16 hx, lx, hy, ly;
                    bsplit(vx, hx, lx); bsplit(vy, hy, ly);
                    __nv_bfloat16* dh = (sec == 0) ? g_Qh : (sec == 1) ? g_Kh : g_Vh;
                    __nv_bfloat16* dl = (sec == 0) ? g_Qlo : (sec == 1) ? g_Klo : g_Vlo;
                    size_t o = ((size_t)bh2 * TSEQ + tt) * DH + dpos;
                    __nv_bfloat162 hv; hv.x = hx; hv.y = hy;
                    __nv_bfloat162 lv; lv.x = lx; lv.y = ly;
                    *(__nv_bfloat162*)(dh + o) = hv;
                    *(__nv_bfloat162*)(dl + o) = lv;
                } else {
                    float2 v2; v2.x = vx; v2.y = vy;
                    *(float2*)(out + (size_t)row * N + col) = v2;
                }
            }
        }
    }
}

// ---------------------------------------------------------------------------
// Tensor-core flash attention, 3xBF16, R14 two-sync mainloop, PAIRED JOBS:
// 256 CTAs; CTA bid runs job bid (heavy) then job 511-bid (light).
// Jobs sorted heavy-first: job j -> qi = 7 - j/64, bh = j%64.
// Pairs sum to 18 tile-units -> single balanced wave at 2 CTAs/SM.
// ---------------------------------------------------------------------------
#define ABQ   128
#define ABK   64
#define SQH 0
#define SQL 16384
#define SKV 32768
#define ASMEM 98304

__device__ __forceinline__ void attn_load_kv(uint32_t sbuf,
        const __nv_bfloat16* Khp, const __nv_bfloat16* Klp,
        const __nv_bfloat16* Vhp, const __nv_bfloat16* Vlp,
        int k0, int tid)
{
#pragma unroll
    for (int l = 0; l < 4; l++) {
        int idx = tid + l * 256;
        int panel = idx >> 9;
        int rem = idx & 511;
        int r = rem >> 3, ch = rem & 7;
        uint32_t off = (uint32_t)r * 128 + ch * 16;
        uint32_t sw = off ^ ((off >> 3) & 0x70);
        cp_async16(sbuf + (panel ? 8192 : 0) + sw,
                   (panel ? Klp : Khp) + (size_t)(k0 + r) * DH + ch * 8);
        cp_async16(sbuf + (panel ? 24576 : 16384) + sw,
                   (panel ? Vlp : Vhp) + (size_t)(k0 + r) * DH + ch * 8);
    }
}

__global__ __launch_bounds__(256, 2) void attn_kernel()
{
    extern __shared__ char smc[];
    const uint32_t sb = smem_u32(smc);

    const int tid  = threadIdx.x;
    const int warp = tid >> 5;
    const int lane = tid & 31;
    const int rA   = lane >> 2;
    const int qcol = (lane & 3) * 2;

    const int acb  = (lane >> 4) & 1;
    const int bcb  = (lane >> 3) & 1;
    const int brow = (lane & 7) + ((lane & 16) >> 1);
    const int koff = (((lane >> 3) & 1) << 3) + (lane & 7);
    const int noct = lane >> 4;

    const float CS = 0.18033688011112042f;

    for (int job = 0; job < 2; job++) {
        const int j  = job ? (511 - (int)blockIdx.x) : (int)blockIdx.x;
        const int qi = 7 - (j >> 6);
        const int bh = j & 63;
        const int bb = bh >> 4, hh = bh & 15;
        const __nv_bfloat16* Qhp = g_Qh  + (size_t)bh * TSEQ * DH;
        const __nv_bfloat16* Qlp = g_Qlo + (size_t)bh * TSEQ * DH;
        const __nv_bfloat16* Khp = g_Kh  + (size_t)bh * TSEQ * DH;
        const __nv_bfloat16* Klp = g_Klo + (size_t)bh * TSEQ * DH;
        const __nv_bfloat16* Vhp = g_Vh  + (size_t)bh * TSEQ * DH;
        const __nv_bfloat16* Vlp = g_Vlo + (size_t)bh * TSEQ * DH;

        // Q panels (hi+lo) + first K/V tile, committed together
#pragma unroll
        for (int l = 0; l < 8; l++) {
            int idx = tid + l * 256;
            int panel = idx >> 10;
            int rem = idx & 1023;
            int r = rem >> 3, ch = rem & 7;
            uint32_t off = (uint32_t)r * 128 + ch * 16;
            uint32_t sw = off ^ ((off >> 3) & 0x70);
            const __nv_bfloat16* src = (panel ? Qlp : Qhp)
                                     + (size_t)(qi * ABQ + r) * DH + ch * 8;
            cp_async16(sb + (panel ? SQL : SQH) + sw, src);
        }
        attn_load_kv(sb + SKV, Khp, Klp, Vhp, Vlp, 0, tid);
        CP_COMMIT();

        float o[8][4];
#pragma unroll
        for (int ni = 0; ni < 8; ni++)
#pragma unroll
            for (int r = 0; r < 4; r++) o[ni][r] = 0.0f;
        float mA = -1e30f, mB = -1e30f, lAcc = 0.0f, lBcc = 0.0f;

        const int ntiles = 2 * qi + 2;

        for (int kt = 0; kt < ntiles; kt++) {
            if (kt + 1 < ntiles) {
                attn_load_kv(sb + SKV + ((kt + 1) & 1) * 32768,
                             Khp, Klp, Vhp, Vlp, (kt + 1) * ABK, tid);
                CP_COMMIT();
                asm volatile("cp.async.wait_group 1;" ::: "memory");
            } else {
                asm volatile("cp.async.wait_group 0;" ::: "memory");
            }
            __syncthreads();

            const uint32_t skv = sb + SKV + (uint32_t)(kt & 1) * 32768;

            if (kt * ABK <= qi * ABQ + warp * 16 + 15) {
                float s[8][4];
#pragma unroll
                for (int ni = 0; ni < 8; ni++)
#pragma unroll
                    for (int r = 0; r < 4; r++) s[ni][r] = 0.0f;

                const int aQrow = warp * 16 + (lane & 15);
                const uint32_t a_ro = (uint32_t)aQrow * 128;
                const int a_rx = aQrow & 7;
#pragma unroll
                for (int ks = 0; ks < 4; ks++) {
                    uint32_t ah[4], al[4], kh[4][4], kl[4][4];
                    uint32_t ao = a_ro + (uint32_t)(((ks * 2 + acb) ^ a_rx) << 4);
                    ldsm_x4(ah, sb + SQH + ao);
                    ldsm_x4(al, sb + SQL + ao);
#pragma unroll
                    for (int pi = 0; pi < 4; pi++) {
                        int br = pi * 16 + brow;
                        uint32_t bo = (uint32_t)br * 128 +
                                      (uint32_t)(((ks * 2 + bcb) ^ (br & 7)) << 4);
                        ldsm_x4(kh[pi], skv + bo);
                        ldsm_x4(kl[pi], skv + 8192 + bo);
                    }
#pragma unroll
                    for (int ni = 0; ni < 8; ni++) {
                        const int pi = ni >> 1, j0 = (ni & 1) * 2;
                        mma_bf16(s[ni], al, kh[pi][j0], kh[pi][j0 + 1]);
                        mma_bf16(s[ni], ah, kl[pi][j0], kl[pi][j0 + 1]);
                        mma_bf16(s[ni], ah, kh[pi][j0], kh[pi][j0 + 1]);
                    }
                }

                const bool needmask = (kt * ABK + ABK - 1 > qi * ABQ + warp * 16);
                const int rowgA = qi * ABQ + warp * 16 + rA;
                const int rowgB = rowgA + 8;
                const int cb = kt * ABK + qcol;
#pragma unroll
                for (int ni = 0; ni < 8; ni++) {
                    float z0 = s[ni][0] * CS, z1 = s[ni][1] * CS;
                    float z2 = s[ni][2] * CS, z3 = s[ni][3] * CS;
                    if (needmask) {
                        int c0 = cb + ni * 8, c1 = c0 + 1;
                        if (c0 > rowgA) z0 = -1e30f;
                        if (c1 > rowgA) z1 = -1e30f;
                        if (c0 > rowgB) z2 = -1e30f;
                        if (c1 > rowgB) z3 = -1e30f;
                    }
                    s[ni][0] = z0; s[ni][1] = z1; s[ni][2] = z2; s[ni][3] = z3;
                }

                float mtA = -1e30f, mtB = -1e30f;
#pragma unroll
                for (int ni = 0; ni < 8; ni++) {
                    mtA = fmaxf(mtA, fmaxf(s[ni][0], s[ni][1]));
                    mtB = fmaxf(mtB, fmaxf(s[ni][2], s[ni][3]));
                }
                mtA = fmaxf(mtA, __shfl_xor_sync(0xffffffffu, mtA, 1));
                mtA = fmaxf(mtA, __shfl_xor_sync(0xffffffffu, mtA, 2));
                mtB = fmaxf(mtB, __shfl_xor_sync(0xffffffffu, mtB, 1));
                mtB = fmaxf(mtB, __shfl_xor_sync(0xffffffffu, mtB, 2));

                const float mnA = fmaxf(mA, mtA);
                const float mnB = fmaxf(mB, mtB);
                const float aAl = fast_exp2(mA - mnA);
                const float aBl = fast_exp2(mB - mnB);
                mA = mnA; mB = mnB;

                float psA = 0.0f, psB = 0.0f;
#pragma unroll
                for (int ni = 0; ni < 8; ni++) {
                    float p0 = fast_exp2(s[ni][0] - mnA);
                    float p1 = fast_exp2(s[ni][1] - mnA);
                    float p2 = fast_exp2(s[ni][2] - mnB);
                    float p3 = fast_exp2(s[ni][3] - mnB);
                    psA += p0 + p1; psB += p2 + p3;
                    s[ni][0] = p0; s[ni][1] = p1; s[ni][2] = p2; s[ni][3] = p3;
                }
                psA += __shfl_xor_sync(0xffffffffu, psA, 1);
                psA += __shfl_xor_sync(0xffffffffu, psA, 2);
                psB += __shfl_xor_sync(0xffffffffu, psB, 1);
                psB += __shfl_xor_sync(0xffffffffu, psB, 2);
                lAcc = lAcc * aAl + psA;
                lBcc = lBcc * aBl + psB;

#pragma unroll
                for (int ni = 0; ni < 8; ni++) {
                    o[ni][0] *= aAl; o[ni][1] *= aAl;
                    o[ni][2] *= aBl; o[ni][3] *= aBl;
                }

#pragma unroll
                for (int jj = 0; jj < 4; jj++) {
                    uint32_t pa_h[4], pa_l[4];
#pragma unroll
                    for (int half = 0; half < 2; half++) {
                        const float* sp = s[2 * jj + half];
                        __nv_bfloat162 h0 = __floats2bfloat162_rn(sp[0], sp[1]);
                        __nv_bfloat162 h1 = __floats2bfloat162_rn(sp[2], sp[3]);
                        __nv_bfloat162 l0 = __floats2bfloat162_rn(
                            sp[0] - __bfloat162float(h0.x), sp[1] - __bfloat162float(h0.y));
                        __nv_bfloat162 l1 = __floats2bfloat162_rn(
                            sp[2] - __bfloat162float(h1.x), sp[3] - __bfloat162float(h1.y));
                        pa_h[half * 2 + 0] = *(uint32_t*)&h0;
                        pa_h[half * 2 + 1] = *(uint32_t*)&h1;
                        pa_l[half * 2 + 0] = *(uint32_t*)&l0;
                        pa_l[half * 2 + 1] = *(uint32_t*)&l1;
                    }

                    uint32_t vh[4][4], vl[4][4];
                    const int vrow = jj * 16 + koff;
                    const uint32_t vro = (uint32_t)vrow * 128;
                    const int v_rx = vrow & 7;
#pragma unroll
                    for (int pi = 0; pi < 4; pi++) {
                        uint32_t chv = (uint32_t)(2 * pi + noct);
                        uint32_t bo = vro + ((chv ^ (uint32_t)v_rx) << 4);
                        ldsm_x4_trans(vh[pi], skv + 16384 + bo);
                        ldsm_x4_trans(vl[pi], skv + 24576 + bo);
                    }
#pragma unroll
                    for (int ni = 0; ni < 8; ni++) {
                        const int pi = ni >> 1, j0 = (ni & 1) * 2;
                        mma_bf16(o[ni], pa_l, vh[pi][j0], vh[pi][j0 + 1]);
                        mma_bf16(o[ni], pa_h, vl[pi][j0], vl[pi][j0 + 1]);
                        mma_bf16(o[ni], pa_h, vh[pi][j0], vh[pi][j0 + 1]);
                    }
                }
            }
            __syncthreads();
        }

        // Epilogue: normalize, split to bf16, write g_Yhi/lo [b][t][c]
        const float invA = 1.0f / lAcc;
        const float invB = 1.0f / lBcc;
        const int tA = qi * ABQ + warp * 16 + rA;
        const int tB = tA + 8;
        const size_t baseA = ((size_t)bb * TSEQ + tA) * CDIM + hh * DH;
        const size_t baseB = ((size_t)bb * TSEQ + tB) * CDIM + hh * DH;
#pragma unroll
        for (int ni = 0; ni < 8; ni++) {
            int col = ni * 8 + qcol;
            float yA0 = o[ni][0] * invA, yA1 = o[ni][1] * invA;
            float yB0 = o[ni][2] * invB, yB1 = o[ni][3] * invB;
            __nv_bfloat16 h0, l0, h1, l1;
            __nv_bfloat162 hv, lv;
            bsplit(yA0, h0, l0); bsplit(yA1, h1, l1);
            hv.x = h0; hv.y = h1; lv.x = l0; lv.y = l1;
            *(__nv_bfloat162*)(g_Yhi + baseA + col) = hv;
            *(__nv_bfloat162*)(g_Ylo + baseA + col) = lv;
            bsplit(yB0, h0, l0); bsplit(yB1, h1, l1);
            hv.x = h0; hv.y = h1; lv.x = l0; lv.y = l1;
            *(__nv_bfloat162*)(g_Yhi + baseB + col) = hv;
            *(__nv_bfloat162*)(g_Ylo + baseB + col) = lv;
        }
        __syncthreads();   // smem fully consumed before next job reuses it
    }
}

// ---------------------------------------------------------------------------
// Launch
// ---------------------------------------------------------------------------
extern "C" void kernel_launch(void* const* d_in, const int* in_sizes, int n_in,
                              void* d_out, int out_size)
{
    const float* x      = (const float*)d_in[0];
    const float* w_attn = (const float*)d_in[1];
    const float* b_attn = (const float*)d_in[2];
    const float* w_proj = (const float*)d_in[3];
    const float* b_proj = (const float*)d_in[4];
    float* out = (float*)d_out;

    // 0) Fused preprocessing (pure splits, no transpose)
    {
        preproc_kernel<<<8192, 256>>>(x, w_attn, w_proj);
    }

    // 1) QKV GEMM (3xbf16, trans-B, BN=64, 3 CTAs/SM)
    {
        constexpr int GS = 3 * (2 * APANEL + 2 * (32 * 64 * 2));   // 73728
        cudaFuncSetAttribute(tc_gemm<3 * CDIM, 0, 64, 3>,
                             cudaFuncAttributeMaxDynamicSharedMemorySize, GS);
        dim3 grid(3 * CDIM / 64, MROWS / GBM);    // (48, 32)
        tc_gemm<3 * CDIM, 0, 64, 3><<<grid, 256, GS>>>(b_attn, nullptr);
    }

    // 2) Tensor-core flash attention (paired persistent jobs, 256 CTAs)
    {
        cudaFuncSetAttribute(attn_kernel,
                             cudaFuncAttributeMaxDynamicSharedMemorySize, ASMEM);
        attn_kernel<<<256, 256, ASMEM>>>();
    }

    // 3) Output projection (3xbf16, trans-B, BN=128, 2 CTAs/SM)
    {
        constexpr int GS = 3 * (2 * APANEL + 2 * (32 * 128 * 2));  // 98304
        cudaFuncSetAttribute(tc_gemm<CDIM, 1, 128, 2>,
                             cudaFuncAttributeMaxDynamicSharedMemorySize, GS);
        dim3 grid(CDIM / 128, MROWS / GBM);       // (8, 32)
        tc_gemm<CDIM, 1, 128, 2><<<grid, 256, GS>>>(b_proj, out);
    }
}